// round 14
// baseline (speedup 1.0000x reference)
#include <cuda_runtime.h>

// Head_3539053052498: B=4, N=4096, H=64, input-dim 1.
// Rank-1 collapse: out[b,q,h] = Wv[h]*r[b,q], r = sum_k p*x_k,
// scores = c*x_q*x_k, c = dot(Wq,Wk)/8, mask: dag[k,q]==0.
// R14: R12 attn (best measured) + fine-grained per-tile producer/consumer:
// attn triggers PDL at start; final CTAs spin on per-tile counters and merge
// as soon as their own tile's 32 chunk-CTAs retire (inside attn's drain).

#define NN  4096
#define BB  4
#define HH  64
#define SPL 32            // k-dimension splits
#define KC  (NN / SPL)    // 128 keys per chunk
#define BLK 256           // threads per CTA in main kernel (1 q per thread)
#define NTILE (NN / BLK)  // 16 q-tiles
#define FROWS 32          // rows per CTA in final kernel
#define FTHR 256          // threads in final kernel
#define FPT  32           // final CTAs per q-tile (BB*BLK/FROWS)

__device__ float2 g_pp[SPL * BB * NN]; // {partial sum, partial weighted sum}
__device__ float  g_cm[SPL * BB];      // per-(chunk,batch) abs-max of X chunk
__device__ int    g_cnt[NTILE];        // attn arrivals per tile (self-reset)
__device__ int    g_done[NTILE];       // final arrivals per tile (self-reset)

__device__ __forceinline__ float ex2(float x) {
    float y;
    asm("ex2.approx.ftz.f32 %0, %1;" : "=f"(y) : "f"(x));
    return y;
}

// ---------------------------------------------------------------------------
// Kernel B — attn, R12 mainloop byte-exact. Trigger at start (ordering is
// enforced by per-tile counters, not PDL); epilogue: stores + fence + arrive.
// ---------------------------------------------------------------------------
__global__ void __launch_bounds__(BLK)
attn_kernel(const float* __restrict__ X, const int* __restrict__ dag,
            const float* __restrict__ Wk, const float* __restrict__ Wq) {
    __shared__ float4 s_x[KC];     // s_x[k] = {X[b][k0+k]}_{b=0..3}
    __shared__ float4 s_rmax[KC];  // reduction scratch
    __shared__ float  s_c;
    __shared__ float4 s_max4;

    // Let the dependent grid start dispatching into spare capacity now.
    cudaTriggerProgrammaticLaunchCompletion();

    const int t  = threadIdx.x;
    const int q  = blockIdx.x * BLK + t;
    const int k0 = blockIdx.y * KC;

    // Warp 0: c = dot(Wq,Wk) * H^-0.5 (H=64 -> /8)
    if (t < 32) {
        float p = Wq[t] * Wk[t] + Wq[t + 32] * Wk[t + 32];
#pragma unroll
        for (int off = 16; off > 0; off >>= 1)
            p += __shfl_xor_sync(0xffffffffu, p, off);
        if (t == 0) s_c = p * 0.125f;
    }

    // Stage chunk of X for all 4 batches (batch-interleaved float4 layout).
#pragma unroll
    for (int i = t; i < KC * BB; i += BLK) {
        int b = i >> 7, k = i & (KC - 1);        // KC = 128
        ((float*)s_x)[k * 4 + b] = X[b * NN + k0 + k];
    }
    __syncthreads();

    // Chunk abs-max per batch (128 float4 -> 1 float4).
    if (t < KC) {
        float4 v = s_x[t];
        s_rmax[t] = make_float4(fabsf(v.x), fabsf(v.y), fabsf(v.z), fabsf(v.w));
    }
    __syncthreads();
    if (t < 32) {
        float4 m = s_rmax[t];
#pragma unroll
        for (int j = 1; j < 4; j++) {
            float4 o = s_rmax[t + j * 32];
            m.x = fmaxf(m.x, o.x); m.y = fmaxf(m.y, o.y);
            m.z = fmaxf(m.z, o.z); m.w = fmaxf(m.w, o.w);
        }
#pragma unroll
        for (int off = 16; off > 0; off >>= 1) {
            m.x = fmaxf(m.x, __shfl_xor_sync(0xffffffffu, m.x, off));
            m.y = fmaxf(m.y, __shfl_xor_sync(0xffffffffu, m.y, off));
            m.z = fmaxf(m.z, __shfl_xor_sync(0xffffffffu, m.z, off));
            m.w = fmaxf(m.w, __shfl_xor_sync(0xffffffffu, m.w, off));
        }
        if (t == 0) s_max4 = m;
    }
    __syncthreads();

    const float LOG2E = 1.4426950408889634f;
    const float c = s_c;
    const float4 cmax = s_max4;
    const float cm[BB] = {cmax.x, cmax.y, cmax.z, cmax.w};

    float a2[BB], nb[BB], sh[BB], sum[BB], wsum[BB];
#pragma unroll
    for (int b = 0; b < BB; b++) {
        float a = c * X[b * NN + q];
        a2[b]   = a * LOG2E;
        sh[b]   = fabsf(a) * cm[b] * LOG2E;  // chunk-local bound (log2 domain)
        nb[b]   = -sh[b];                    // => exp2 arg <= 0, overflow-proof
        sum[b]  = 0.f;
        wsum[b] = 0.f;
    }

    const int* dp = dag + (size_t)k0 * NN + q;
#pragma unroll 8
    for (int k = 0; k < KC; k++) {
        float4 xv = s_x[k];          // LDS.128, warp-uniform broadcast
        int m = __ldcs(dp);          // dag[k0+k][q], streaming, coalesced
        dp += NN;
        float e0 = ex2(fmaf(a2[0], xv.x, nb[0]));
        float e1 = ex2(fmaf(a2[1], xv.y, nb[1]));
        float e2 = ex2(fmaf(a2[2], xv.z, nb[2]));
        float e3 = ex2(fmaf(a2[3], xv.w, nb[3]));
        if (m) {                     // predicated FADD/FFMA, no divergence
            sum[0] += e0; wsum[0] = fmaf(e0, xv.x, wsum[0]);
            sum[1] += e1; wsum[1] = fmaf(e1, xv.y, wsum[1]);
            sum[2] += e2; wsum[2] = fmaf(e2, xv.z, wsum[2]);
            sum[3] += e3; wsum[3] = fmaf(e3, xv.w, wsum[3]);
        }
    }

    const int s = blockIdx.y;
#pragma unroll
    for (int b = 0; b < BB; b++) {
        int idx = (s * BB + b) * NN + q;
        g_pp[idx] = make_float2(sum[b], wsum[b]);   // STG.64
    }
    if (t == 0) {
#pragma unroll
        for (int b = 0; b < BB; b++) g_cm[s * BB + b] = cm[b];
    }

    // Release: all stores visible, then arrive on this tile's counter.
    __threadfence();
    __syncthreads();
    if (t == 0) atomicAdd(&g_cnt[blockIdx.x], 1);
}

// ---------------------------------------------------------------------------
// Kernel C (PDL secondary): CTA owns 32 rows of one q-tile. Prologue (Wv, X,
// c from Wq.Wk) overlaps attn; then spin until this tile's 32 producers have
// arrived; merge; write; self-reset counters via g_done.
// ---------------------------------------------------------------------------
__global__ void __launch_bounds__(FTHR)
final_kernel(const float* __restrict__ X, const float* __restrict__ Wk,
             const float* __restrict__ Wq, const float* __restrict__ Wv,
             float* __restrict__ out) {
    __shared__ float2 s_pp[SPL][FROWS];
    __shared__ float  s_cm[SPL];
    __shared__ float  s_r[FROWS];
    __shared__ float4 s_wv[HH / 4];
    __shared__ float  s_c;

    const int t  = threadIdx.x;
    const int w0 = blockIdx.x * FROWS;      // rows w0..w0+31, all in batch b
    const int b  = w0 >> 12;                // NN = 4096
    const int q0 = w0 & (NN - 1);
    const int T  = q0 >> 8;                 // q-tile index (BLK = 256)

    // ---- independent prologue (overlaps attn) ----
    if (t < HH / 4) s_wv[t] = ((const float4*)Wv)[t];
    float xq = 0.f;
    if (t < FROWS) xq = X[b * NN + q0 + t];   // harness input: stable
    if (t >= 32 && t < 64) {                  // warp 1: c = dot(Wq,Wk)/8
        int l = t - 32;
        float p = Wq[l] * Wk[l] + Wq[l + 32] * Wk[l + 32];
#pragma unroll
        for (int off = 16; off > 0; off >>= 1)
            p += __shfl_xor_sync(0xffffffffu, p, off);
        if (l == 0) s_c = p * 0.125f;
    }

    // ---- wait for THIS tile's 32 producer CTAs (not the whole grid) ----
    if (t == 0) {
        while (atomicAdd(&g_cnt[T], 0) < SPL) __nanosleep(200);
        __threadfence();   // acquire: order subsequent reads after arrivals
    }
    __syncthreads();

    if (t >= 64 && t < 96) s_cm[t - 64] = g_cm[(t - 64) * BB + b];

    // Coalesced float2 staging: SPL*FROWS elements, 4 per thread.
#pragma unroll
    for (int i = t; i < SPL * FROWS; i += FTHR) {
        int s = i >> 5, w = i & (FROWS - 1);
        s_pp[s][w] = g_pp[s * BB * NN + w0 + w];
    }
    __syncthreads();

    // Warp 0: row-per-lane split-softmax merge with recomputed shifts.
    if (t < FROWS) {
        const float LOG2E = 1.4426950408889634f;
        float aL = fabsf(s_c * xq) * LOG2E;
        float cmax = 0.f;
#pragma unroll
        for (int s = 0; s < SPL; s++) cmax = fmaxf(cmax, s_cm[s]);
        float ssum = 0.f, wsum = 0.f;
#pragma unroll
        for (int s = 0; s < SPL; s++) {
            float f = ex2(aL * (s_cm[s] - cmax));   // <= 1
            float2 p = s_pp[s][t];
            ssum = fmaf(p.x, f, ssum);
            wsum = fmaf(p.y, f, wsum);
        }
        s_r[t] = (ssum != 0.f) ? (wsum / ssum) : 0.f;  // fully-masked row -> 0
    }
    __syncthreads();

    // Coalesced broadcast write: FROWS rows x 16 float4 (2 per thread).
    float4* out4 = (float4*)out + (size_t)w0 * (HH / 4);
#pragma unroll
    for (int i = t; i < FROWS * (HH / 4); i += FTHR) {
        int row = i >> 4, h4 = i & 15;
        float r = s_r[row];
        float4 v = s_wv[h4];
        out4[i] = make_float4(r * v.x, r * v.y, r * v.z, r * v.w);
    }

    // ---- self-reset for graph replay: 32nd consumer clears both counters.
    __syncthreads();
    if (t == 0) {
        int prev = atomicAdd(&g_done[T], 1);
        if (prev == FPT - 1) {
            atomicExch(&g_cnt[T], 0);
            atomicExch(&g_done[T], 0);
        }
    }
}

// ---------------------------------------------------------------------------
extern "C" void kernel_launch(void* const* d_in, const int* in_sizes, int n_in,
                              void* d_out, int out_size) {
    const float* X   = (const float*)d_in[0];
    const int*   dag = (const int*)d_in[1];
    const float* Wk  = (const float*)d_in[2];
    const float* Wq  = (const float*)d_in[3];
    const float* Wv  = (const float*)d_in[4];
    float* out = (float*)d_out;

    attn_kernel<<<dim3(NTILE, SPL), BLK>>>(X, dag, Wk, Wq);

    // Secondary launch with programmatic (PDL) dependency on attn_kernel.
    cudaLaunchAttribute attrs[1];
    attrs[0].id = cudaLaunchAttributeProgrammaticStreamSerialization;
    attrs[0].val.programmaticStreamSerializationAllowed = 1;
    cudaLaunchConfig_t cfg = {};
    cfg.gridDim  = dim3((BB * NN) / FROWS, 1, 1);
    cfg.blockDim = dim3(FTHR, 1, 1);
    cfg.dynamicSmemBytes = 0;
    cfg.stream = 0;
    cfg.attrs = attrs;
    cfg.numAttrs = 1;
    cudaLaunchKernelEx(&cfg, final_kernel, X, Wk, Wq, Wv, out);
}

// round 16
// speedup vs baseline: 1.1529x; 1.1529x over previous
#include <cuda_runtime.h>

// Head_3539053052498: B=4, N=4096, H=64, input-dim 1.
// Rank-1 collapse: out[b,q,h] = Wv[h]*r[b,q], r = sum_k p*x_k,
// scores = c*x_q*x_k, c = dot(Wq,Wk)/8, mask: dag[k,q]==0.
// R16 = R15 resubmitted verbatim (R15 bench was an infra failure).
// R12 structure (best measured, 30.7us) + software-pipelined dag-mask
// prefetch (double-buffered groups of 8 -> per-warp MLP ~8). The dag stream
// was measured at 1.65TB/s with nothing saturated => DRAM-latency x MLP bound.

#define NN  4096
#define BB  4
#define HH  64
#define SPL 32            // k-dimension splits
#define KC  (NN / SPL)    // 128 keys per chunk
#define GRP 8             // prefetch group size
#define NGRP (KC / GRP)   // 16 groups
#define BLK 256           // threads per CTA in main kernel (1 q per thread)
#define FROWS 32          // rows per CTA in final kernel
#define FTHR 256          // threads in final kernel

__device__ float2 g_pp[SPL * BB * NN]; // {partial sum, partial weighted sum}
__device__ float  g_cm[SPL * BB];      // per-(chunk,batch) abs-max of X chunk
__device__ float  g_c;                 // dot(Wq,Wk)/8 (same value from all writers)

__device__ __forceinline__ float ex2(float x) {
    float y;
    asm("ex2.approx.ftz.f32 %0, %1;" : "=f"(y) : "f"(x));
    return y;
}

// ---------------------------------------------------------------------------
// Kernel B — attn. R12 except the mainloop mask loads are double-buffered.
// ---------------------------------------------------------------------------
__global__ void __launch_bounds__(BLK)
attn_kernel(const float* __restrict__ X, const int* __restrict__ dag,
            const float* __restrict__ Wk, const float* __restrict__ Wq) {
    __shared__ float4 s_x[KC];     // s_x[k] = {X[b][k0+k]}_{b=0..3}
    __shared__ float4 s_rmax[KC];  // reduction scratch
    __shared__ float  s_c;
    __shared__ float4 s_max4;

    const int t  = threadIdx.x;
    const int q  = blockIdx.x * BLK + t;
    const int k0 = blockIdx.y * KC;

    // Warp 0: c = dot(Wq,Wk) * H^-0.5 (H=64 -> /8)
    if (t < 32) {
        float p = Wq[t] * Wk[t] + Wq[t + 32] * Wk[t + 32];
#pragma unroll
        for (int off = 16; off > 0; off >>= 1)
            p += __shfl_xor_sync(0xffffffffu, p, off);
        if (t == 0) s_c = p * 0.125f;
    }

    // Stage chunk of X for all 4 batches (batch-interleaved float4 layout).
#pragma unroll
    for (int i = t; i < KC * BB; i += BLK) {
        int b = i >> 7, k = i & (KC - 1);        // KC = 128
        ((float*)s_x)[k * 4 + b] = X[b * NN + k0 + k];
    }
    __syncthreads();

    // Chunk abs-max per batch (128 float4 -> 1 float4).
    if (t < KC) {
        float4 v = s_x[t];
        s_rmax[t] = make_float4(fabsf(v.x), fabsf(v.y), fabsf(v.z), fabsf(v.w));
    }
    __syncthreads();
    if (t < 32) {
        float4 m = s_rmax[t];
#pragma unroll
        for (int j = 1; j < 4; j++) {
            float4 o = s_rmax[t + j * 32];
            m.x = fmaxf(m.x, o.x); m.y = fmaxf(m.y, o.y);
            m.z = fmaxf(m.z, o.z); m.w = fmaxf(m.w, o.w);
        }
#pragma unroll
        for (int off = 16; off > 0; off >>= 1) {
            m.x = fmaxf(m.x, __shfl_xor_sync(0xffffffffu, m.x, off));
            m.y = fmaxf(m.y, __shfl_xor_sync(0xffffffffu, m.y, off));
            m.z = fmaxf(m.z, __shfl_xor_sync(0xffffffffu, m.z, off));
            m.w = fmaxf(m.w, __shfl_xor_sync(0xffffffffu, m.w, off));
        }
        if (t == 0) s_max4 = m;
    }
    __syncthreads();

    const float LOG2E = 1.4426950408889634f;
    const float c = s_c;
    const float4 cmax = s_max4;
    const float cm[BB] = {cmax.x, cmax.y, cmax.z, cmax.w};

    float a2[BB], nb[BB], sh[BB], sum[BB], wsum[BB];
#pragma unroll
    for (int b = 0; b < BB; b++) {
        float a = c * X[b * NN + q];
        a2[b]   = a * LOG2E;
        sh[b]   = fabsf(a) * cm[b] * LOG2E;  // chunk-local bound (log2 domain)
        nb[b]   = -sh[b];                    // => exp2 arg <= 0, overflow-proof
        sum[b]  = 0.f;
        wsum[b] = 0.f;
    }

    // ---- mainloop with double-buffered mask prefetch (MLP ~= GRP) ----
    const int* dp = dag + (size_t)k0 * NN + q;   // current group base
    int mcur[GRP], mnxt[GRP];
#pragma unroll
    for (int j = 0; j < GRP; j++) mcur[j] = __ldcs(dp + j * NN);

#pragma unroll
    for (int g = 0; g < NGRP; g++) {
        // Prefetch next group (last group re-loads itself; stays in bounds).
        const int* pf = dp + ((g < NGRP - 1) ? GRP * NN : 0);
#pragma unroll
        for (int j = 0; j < GRP; j++) mnxt[j] = __ldcs(pf + j * NN);

#pragma unroll
        for (int j = 0; j < GRP; j++) {
            float4 xv = s_x[g * GRP + j];   // LDS.128, warp-uniform broadcast
            int m = mcur[j];
            float e0 = ex2(fmaf(a2[0], xv.x, nb[0]));
            float e1 = ex2(fmaf(a2[1], xv.y, nb[1]));
            float e2 = ex2(fmaf(a2[2], xv.z, nb[2]));
            float e3 = ex2(fmaf(a2[3], xv.w, nb[3]));
            if (m) {                 // predicated FADD/FFMA, no divergence
                sum[0] += e0; wsum[0] = fmaf(e0, xv.x, wsum[0]);
                sum[1] += e1; wsum[1] = fmaf(e1, xv.y, wsum[1]);
                sum[2] += e2; wsum[2] = fmaf(e2, xv.z, wsum[2]);
                sum[3] += e3; wsum[3] = fmaf(e3, xv.w, wsum[3]);
            }
        }
#pragma unroll
        for (int j = 0; j < GRP; j++) mcur[j] = mnxt[j];
        dp += GRP * NN;
    }

    const int s = blockIdx.y;
#pragma unroll
    for (int b = 0; b < BB; b++) {
        int idx = (s * BB + b) * NN + q;
        g_pp[idx] = make_float2(sum[b], wsum[b]);   // STG.64
    }
    if (t == 0) {
#pragma unroll
        for (int b = 0; b < BB; b++) g_cm[s * BB + b] = cm[b];
        if (blockIdx.x == 0 && s == 0) g_c = c;  // same value deterministically
    }

    // PDL: allow the dependent final_kernel grid to begin dispatch.
    cudaTriggerProgrammaticLaunchCompletion();
}

// ---------------------------------------------------------------------------
// Kernel C (PDL secondary): identical to R12.
// ---------------------------------------------------------------------------
__global__ void __launch_bounds__(FTHR)
final_kernel(const float* __restrict__ X, const float* __restrict__ Wv,
             float* __restrict__ out) {
    __shared__ float2 s_pp[SPL][FROWS];
    __shared__ float  s_cm[SPL];
    __shared__ float  s_r[FROWS];
    __shared__ float4 s_wv[HH / 4];

    const int t  = threadIdx.x;
    const int w0 = blockIdx.x * FROWS;      // rows w0..w0+31, all in batch b
    const int b  = w0 >> 12;                // NN = 4096
    const int q0 = w0 & (NN - 1);

    // ---- independent prologue (overlaps attn's tail) ----
    if (t < HH / 4) s_wv[t] = ((const float4*)Wv)[t];
    float xq = 0.f;
    if (t < FROWS) xq = X[b * NN + q0 + t];   // X is a harness input: stable

    // ---- wait for attn's writes to be visible ----
    cudaGridDependencySynchronize();

    if (t >= 64 && t < 96) s_cm[t - 64] = g_cm[(t - 64) * BB + b];

    // Coalesced float2 staging: SPL*FROWS elements, 4 per thread.
#pragma unroll
    for (int i = t; i < SPL * FROWS; i += FTHR) {
        int s = i >> 5, w = i & (FROWS - 1);
        s_pp[s][w] = g_pp[s * BB * NN + w0 + w];
    }
    __syncthreads();

    // Warp 0: row-per-lane split-softmax merge with recomputed shifts.
    if (t < FROWS) {
        const float LOG2E = 1.4426950408889634f;
        float aL = fabsf(g_c * xq) * LOG2E;
        float cmax = 0.f;
#pragma unroll
        for (int s = 0; s < SPL; s++) cmax = fmaxf(cmax, s_cm[s]);
        float ssum = 0.f, wsum = 0.f;
#pragma unroll
        for (int s = 0; s < SPL; s++) {
            float f = ex2(aL * (s_cm[s] - cmax));   // <= 1
            float2 p = s_pp[s][t];
            ssum = fmaf(p.x, f, ssum);
            wsum = fmaf(p.y, f, wsum);
        }
        s_r[t] = (ssum != 0.f) ? (wsum / ssum) : 0.f;  // fully-masked row -> 0
    }
    __syncthreads();

    // Coalesced broadcast write: FROWS rows x 16 float4 (2 per thread).
    float4* out4 = (float4*)out + (size_t)w0 * (HH / 4);
#pragma unroll
    for (int i = t; i < FROWS * (HH / 4); i += FTHR) {
        int row = i >> 4, h4 = i & 15;
        float r = s_r[row];
        float4 v = s_wv[h4];
        out4[i] = make_float4(r * v.x, r * v.y, r * v.z, r * v.w);
    }
}

// ---------------------------------------------------------------------------
extern "C" void kernel_launch(void* const* d_in, const int* in_sizes, int n_in,
                              void* d_out, int out_size) {
    const float* X   = (const float*)d_in[0];
    const int*   dag = (const int*)d_in[1];
    const float* Wk  = (const float*)d_in[2];
    const float* Wq  = (const float*)d_in[3];
    const float* Wv  = (const float*)d_in[4];
    float* out = (float*)d_out;

    attn_kernel<<<dim3(NN / BLK, SPL), BLK>>>(X, dag, Wk, Wq);

    // Secondary launch with programmatic (PDL) dependency on attn_kernel.
    cudaLaunchAttribute attrs[1];
    attrs[0].id = cudaLaunchAttributeProgrammaticStreamSerialization;
    attrs[0].val.programmaticStreamSerializationAllowed = 1;
    cudaLaunchConfig_t cfg = {};
    cfg.gridDim  = dim3((BB * NN) / FROWS, 1, 1);
    cfg.blockDim = dim3(FTHR, 1, 1);
    cfg.dynamicSmemBytes = 0;
    cfg.stream = 0;
    cfg.attrs = attrs;
    cfg.numAttrs = 1;
    cudaLaunchKernelEx(&cfg, final_kernel, X, Wv, out);
}